// round 1
// baseline (speedup 1.0000x reference)
#include <cuda_runtime.h>
#include <math.h>

#define BB  2048
#define SS  512
#define EE  384
#define FF  28
#define HH  32
#define SP1 513          // S+1 positions (trainable prefix + S)
#define NW  16           // warps per block
#define NT  512          // threads per block

__device__ __forceinline__ float warp_sum(float v) {
    #pragma unroll
    for (int o = 16; o; o >>= 1) v += __shfl_xor_sync(0xffffffffu, v, o);
    return v;
}

__global__ __launch_bounds__(NT, 2)
void sent_attn_kernel(const float* __restrict__ emb,        // [B,S,E]
                      const int*   __restrict__ masks,      // [B,S]
                      const float* __restrict__ features,   // [B,F]
                      const float* __restrict__ W_map,      // [F,H]
                      const float* __restrict__ b_map,      // [H]
                      const float* __restrict__ trainable,  // [1,E]
                      const float* __restrict__ W_k,        // [E,H]
                      const float* __restrict__ b_k,        // [H]
                      const float* __restrict__ W_v,        // [E,H]
                      const float* __restrict__ b_v,        // [H]
                      const float* __restrict__ W_c,        // [2H,1]
                      const float* __restrict__ b_c,        // [1]
                      float*       __restrict__ out)        // [B] logits ++ [B,SP1] attn
{
    __shared__ __align__(16) float s_qk[EE];
    __shared__ __align__(16) float s_norm[EE];
    __shared__ __align__(16) float s_acc[NW][EE];
    __shared__ __align__(16) float s_ctx[EE];
    __shared__ float s_q[HH];
    __shared__ float s_scores[SP1];
    __shared__ float s_wm[NW], s_wd[NW], s_wscale[NW];
    __shared__ float s_doc[NW][HH];
    __shared__ float s_dotqbk, s_gm, s_gd;

    const int b    = blockIdx.x;
    const int tid  = threadIdx.x;
    const int w    = tid >> 5;
    const int lane = tid & 31;

    // ---------------- prologue: q = features@W_map + b_map ; normed trainable ----
    if (w == 0) {
        float acc = b_map[lane];
        const float* fb = features + b * FF;
        #pragma unroll
        for (int f = 0; f < FF; ++f)
            acc = fmaf(fb[f], W_map[f * HH + lane], acc);
        s_q[lane] = acc;
    } else if (w == 1) {
        float ss = 0.f;
        #pragma unroll
        for (int j = 0; j < EE / 32; ++j) {
            float t = trainable[lane + 32 * j];
            ss = fmaf(t, t, ss);
        }
        ss = warp_sum(ss);
        float inv = rsqrtf(ss);
        #pragma unroll
        for (int j = 0; j < EE / 32; ++j)
            s_norm[lane + 32 * j] = trainable[lane + 32 * j] * inv;
    }
    __syncthreads();

    // qk = W_k @ q  (per-e warp reduction, coalesced W_k reads, L2-resident)
    {
        float qv = s_q[lane];
        #pragma unroll
        for (int i = 0; i < EE / NW; ++i) {          // 24 iterations
            int e = w + i * NW;
            float p = W_k[e * HH + lane] * qv;
            p = warp_sum(p);
            if (lane == 0) s_qk[e] = p;
        }
    }
    if (tid == 0) {
        float acc = 0.f;
        #pragma unroll
        for (int h = 0; h < HH; ++h) acc = fmaf(s_q[h], b_k[h], acc);
        s_dotqbk = acc;
    }
    __syncthreads();

    // ---------------- single pass over positions with online softmax ------------
    const float dq    = s_dotqbk;
    const float scale = 0.17677669529663687f;        // 1/sqrt(32)
    const float4* qk4 = (const float4*)s_qk;
    float4 k0 = qk4[lane], k1 = qk4[lane + 32], k2 = qk4[lane + 64];

    float  m = -INFINITY, dsum = 0.f;
    float4 a0 = {0.f,0.f,0.f,0.f}, a1 = {0.f,0.f,0.f,0.f}, a2 = {0.f,0.f,0.f,0.f};

    const int*    mrow      = masks + (size_t)b * SS;
    const float4* erow_base = (const float4*)emb + (size_t)b * SS * (EE / 4);

    for (int s = w; s < SP1; s += NW) {
        float4 v0, v1, v2;
        int mk;
        if (s == 0) {
            const float4* n4 = (const float4*)s_norm;
            v0 = n4[lane]; v1 = n4[lane + 32]; v2 = n4[lane + 64];
            mk = 0;
        } else {
            const float4* r = erow_base + (size_t)(s - 1) * (EE / 4);
            v0 = r[lane]; v1 = r[lane + 32]; v2 = r[lane + 64];
            mk = mrow[s - 1];
        }
        float p = v0.x*k0.x + v0.y*k0.y + v0.z*k0.z + v0.w*k0.w;
        p      += v1.x*k1.x + v1.y*k1.y + v1.z*k1.z + v1.w*k1.w;
        p      += v2.x*k2.x + v2.y*k2.y + v2.z*k2.z + v2.w*k2.w;
        p = warp_sum(p);

        float score = mk ? -INFINITY : (p + dq) * scale;
        if (lane == 0) s_scores[s] = score;

        if (!mk) {
            if (score <= m) {
                float wt = __expf(score - m);
                dsum += wt;
                a0.x = fmaf(wt, v0.x, a0.x); a0.y = fmaf(wt, v0.y, a0.y);
                a0.z = fmaf(wt, v0.z, a0.z); a0.w = fmaf(wt, v0.w, a0.w);
                a1.x = fmaf(wt, v1.x, a1.x); a1.y = fmaf(wt, v1.y, a1.y);
                a1.z = fmaf(wt, v1.z, a1.z); a1.w = fmaf(wt, v1.w, a1.w);
                a2.x = fmaf(wt, v2.x, a2.x); a2.y = fmaf(wt, v2.y, a2.y);
                a2.z = fmaf(wt, v2.z, a2.z); a2.w = fmaf(wt, v2.w, a2.w);
            } else {
                float c = __expf(m - score);   // exp(-inf)=0 handles first hit
                m = score;
                dsum = fmaf(dsum, c, 1.f);
                a0.x = fmaf(a0.x, c, v0.x); a0.y = fmaf(a0.y, c, v0.y);
                a0.z = fmaf(a0.z, c, v0.z); a0.w = fmaf(a0.w, c, v0.w);
                a1.x = fmaf(a1.x, c, v1.x); a1.y = fmaf(a1.y, c, v1.y);
                a1.z = fmaf(a1.z, c, v1.z); a1.w = fmaf(a1.w, c, v1.w);
                a2.x = fmaf(a2.x, c, v2.x); a2.y = fmaf(a2.y, c, v2.y);
                a2.z = fmaf(a2.z, c, v2.z); a2.w = fmaf(a2.w, c, v2.w);
            }
        }
    }

    if (lane == 0) { s_wm[w] = m; s_wd[w] = dsum; }
    {
        float4* arow = (float4*)s_acc[w];
        arow[lane] = a0; arow[lane + 32] = a1; arow[lane + 64] = a2;
    }
    __syncthreads();

    // ---------------- merge the 16 warp-local softmax states ---------------------
    if (w == 0) {
        float mm = (lane < NW) ? s_wm[lane] : -INFINITY;
        #pragma unroll
        for (int o = 16; o; o >>= 1)
            mm = fmaxf(mm, __shfl_xor_sync(0xffffffffu, mm, o));
        float sc = 0.f, dd = 0.f;
        if (lane < NW) {
            sc = __expf(s_wm[lane] - mm);       // 0 if warp was fully masked
            s_wscale[lane] = sc;
            dd = s_wd[lane] * sc;
        }
        dd = warp_sum(dd);
        if (lane == 0) { s_gm = mm; s_gd = dd; }
    }
    __syncthreads();

    const float gm   = s_gm;
    const float ginv = 1.f / s_gd;

    // ctx[e] = sum_w wscale[w] * acc[w][e] / d
    if (tid < EE) {
        float c = 0.f;
        #pragma unroll
        for (int ww = 0; ww < NW; ++ww)
            c = fmaf(s_wscale[ww], s_acc[ww][tid], c);
        s_ctx[tid] = c * ginv;
    }

    // attn_weight output (masked -> exp(-inf)=0 exactly)
    {
        float* out_attn = out + BB + (size_t)b * SP1;
        for (int s = tid; s < SP1; s += NT)
            out_attn[s] = __expf(s_scores[s] - gm) * ginv;
    }
    __syncthreads();

    // ---------------- doc_repr = ctx @ W_v + b_v ; logits ------------------------
    {
        const int g  = w, h = lane;
        const int e0 = g * (EE / NW);               // 24-wide slabs
        float p = 0.f;
        #pragma unroll
        for (int j = 0; j < EE / NW; ++j)
            p = fmaf(s_ctx[e0 + j], W_v[(e0 + j) * HH + h], p);
        s_doc[g][h] = p;
    }
    __syncthreads();
    if (w == 0) {
        float dv = b_v[lane];
        #pragma unroll
        for (int g = 0; g < NW; ++g) dv += s_doc[g][lane];
        float lg = fmaf(dv, W_c[lane], s_q[lane] * W_c[HH + lane]);
        lg = warp_sum(lg);
        if (lane == 0) out[b] = lg + b_c[0];
    }
}

extern "C" void kernel_launch(void* const* d_in, const int* in_sizes, int n_in,
                              void* d_out, int out_size) {
    (void)in_sizes; (void)n_in; (void)out_size;
    sent_attn_kernel<<<BB, NT>>>(
        (const float*)d_in[0],   // embeddings
        (const int*  )d_in[1],   // masks
        (const float*)d_in[2],   // features
        (const float*)d_in[3],   // W_map
        (const float*)d_in[4],   // b_map
        (const float*)d_in[5],   // trainable
        (const float*)d_in[6],   // W_k
        (const float*)d_in[7],   // b_k
        (const float*)d_in[8],   // W_v
        (const float*)d_in[9],   // b_v
        (const float*)d_in[10],  // W_c
        (const float*)d_in[11],  // b_c
        (float*)d_out);
}

// round 2
// speedup vs baseline: 1.5728x; 1.5728x over previous
#include <cuda_runtime.h>
#include <math.h>

#define BB  2048
#define SS  512
#define EE  384
#define FF  28
#define HH  32
#define SP1 513          // S+1 positions (trainable prefix + S)
#define NW  16           // warps per block
#define NT  512          // threads per block

__device__ __forceinline__ float warp_sum(float v) {
    #pragma unroll
    for (int o = 16; o; o >>= 1) v += __shfl_xor_sync(0xffffffffu, v, o);
    return v;
}

__global__ __launch_bounds__(NT, 2)
void sent_attn_kernel(const float* __restrict__ emb,        // [B,S,E]
                      const int*   __restrict__ masks,      // [B,S]
                      const float* __restrict__ features,   // [B,F]
                      const float* __restrict__ W_map,      // [F,H]
                      const float* __restrict__ b_map,      // [H]
                      const float* __restrict__ trainable,  // [1,E]
                      const float* __restrict__ W_k,        // [E,H]
                      const float* __restrict__ b_k,        // [H]
                      const float* __restrict__ W_v,        // [E,H]
                      const float* __restrict__ b_v,        // [H]
                      const float* __restrict__ W_c,        // [2H,1]
                      const float* __restrict__ b_c,        // [1]
                      float*       __restrict__ out)        // [B] logits ++ [B,SP1] attn
{
    __shared__ __align__(16) float s_qk[EE];
    __shared__ __align__(16) float s_norm[EE];
    __shared__ __align__(16) float s_acc[NW][EE];
    __shared__ __align__(16) float s_ctx[EE];
    __shared__ float s_q[HH];
    __shared__ float s_scores[SP1];
    __shared__ int   s_mask[SS];
    __shared__ float s_wm[NW], s_wd[NW], s_wscale[NW];
    __shared__ float s_doc[NW][HH];
    __shared__ float s_dotqbk, s_gm, s_gd;

    const int b    = blockIdx.x;
    const int tid  = threadIdx.x;
    const int w    = tid >> 5;
    const int lane = tid & 31;

    // ---------------- prologue -------------------------------------------------
    // stage masks (coalesced, all threads)
    {
        const int* mrow = masks + (size_t)b * SS;
        s_mask[tid] = mrow[tid];                 // NT == SS == 512
    }
    if (w == 0) {
        float acc = b_map[lane];
        const float* fb = features + b * FF;
        #pragma unroll
        for (int f = 0; f < FF; ++f)
            acc = fmaf(fb[f], W_map[f * HH + lane], acc);
        s_q[lane] = acc;
    } else if (w == 1) {
        float ss = 0.f;
        #pragma unroll
        for (int j = 0; j < EE / 32; ++j) {
            float t = trainable[lane + 32 * j];
            ss = fmaf(t, t, ss);
        }
        ss = warp_sum(ss);
        float inv = rsqrtf(ss);
        #pragma unroll
        for (int j = 0; j < EE / 32; ++j)
            s_norm[lane + 32 * j] = trainable[lane + 32 * j] * inv;
    }
    __syncthreads();

    // qk = W_k @ q  (L2-resident weights)
    {
        float qv = s_q[lane];
        #pragma unroll
        for (int i = 0; i < EE / NW; ++i) {          // 24 iterations
            int e = w + i * NW;
            float p = W_k[e * HH + lane] * qv;
            p = warp_sum(p);
            if (lane == 0) s_qk[e] = p;
        }
    }
    if (tid == 0) {
        float acc = 0.f;
        #pragma unroll
        for (int h = 0; h < HH; ++h) acc = fmaf(s_q[h], b_k[h], acc);
        s_dotqbk = acc;
    }
    __syncthreads();

    // ---------------- single pass with online softmax + mask skipping ----------
    const float dq    = s_dotqbk;
    const float scale = 0.17677669529663687f;        // 1/sqrt(32)
    const float4* qk4 = (const float4*)s_qk;
    float4 k0 = qk4[lane], k1 = qk4[lane + 32], k2 = qk4[lane + 64];

    float  m = -INFINITY, dsum = 0.f;
    float4 a0 = {0.f,0.f,0.f,0.f}, a1 = {0.f,0.f,0.f,0.f}, a2 = {0.f,0.f,0.f,0.f};

    // warp 0 seeds its state with the (never-masked) trainable prefix position
    if (w == 0) {
        const float4* n4 = (const float4*)s_norm;
        float4 v0 = n4[lane], v1 = n4[lane + 32], v2 = n4[lane + 64];
        float p = v0.x*k0.x + v0.y*k0.y + v0.z*k0.z + v0.w*k0.w;
        p      += v1.x*k1.x + v1.y*k1.y + v1.z*k1.z + v1.w*k1.w;
        p      += v2.x*k2.x + v2.y*k2.y + v2.z*k2.z + v2.w*k2.w;
        p = warp_sum(p);
        float score = (p + dq) * scale;
        if (lane == 0) s_scores[0] = score;
        m = score; dsum = 1.f;
        a0 = v0; a1 = v1; a2 = v2;
    }

    const float4* erow_base = (const float4*)emb + (size_t)b * SS * (EE / 4);

    #pragma unroll 2
    for (int i = 0; i < SS / NW; ++i) {              // 32 iterations, fixed trip
        const int s  = w + i * NW;                   // emb row 0..511
        const int mk = s_mask[s];
        if (mk) {
            if (lane == 0) s_scores[s + 1] = -INFINITY;
            continue;                                 // row never read from HBM
        }
        const float4* r = erow_base + (size_t)s * (EE / 4);
        float4 v0 = __ldcs(r + lane);
        float4 v1 = __ldcs(r + lane + 32);
        float4 v2 = __ldcs(r + lane + 64);

        float p = v0.x*k0.x + v0.y*k0.y + v0.z*k0.z + v0.w*k0.w;
        p      += v1.x*k1.x + v1.y*k1.y + v1.z*k1.z + v1.w*k1.w;
        p      += v2.x*k2.x + v2.y*k2.y + v2.z*k2.z + v2.w*k2.w;
        p = warp_sum(p);

        float score = (p + dq) * scale;
        if (lane == 0) s_scores[s + 1] = score;

        if (score <= m) {
            float wt = __expf(score - m);
            dsum += wt;
            a0.x = fmaf(wt, v0.x, a0.x); a0.y = fmaf(wt, v0.y, a0.y);
            a0.z = fmaf(wt, v0.z, a0.z); a0.w = fmaf(wt, v0.w, a0.w);
            a1.x = fmaf(wt, v1.x, a1.x); a1.y = fmaf(wt, v1.y, a1.y);
            a1.z = fmaf(wt, v1.z, a1.z); a1.w = fmaf(wt, v1.w, a1.w);
            a2.x = fmaf(wt, v2.x, a2.x); a2.y = fmaf(wt, v2.y, a2.y);
            a2.z = fmaf(wt, v2.z, a2.z); a2.w = fmaf(wt, v2.w, a2.w);
        } else {
            float c = __expf(m - score);             // exp(-inf)=0 on first hit
            m = score;
            dsum = fmaf(dsum, c, 1.f);
            a0.x = fmaf(a0.x, c, v0.x); a0.y = fmaf(a0.y, c, v0.y);
            a0.z = fmaf(a0.z, c, v0.z); a0.w = fmaf(a0.w, c, v0.w);
            a1.x = fmaf(a1.x, c, v1.x); a1.y = fmaf(a1.y, c, v1.y);
            a1.z = fmaf(a1.z, c, v1.z); a1.w = fmaf(a1.w, c, v1.w);
            a2.x = fmaf(a2.x, c, v2.x); a2.y = fmaf(a2.y, c, v2.y);
            a2.z = fmaf(a2.z, c, v2.z); a2.w = fmaf(a2.w, c, v2.w);
        }
    }

    if (lane == 0) { s_wm[w] = m; s_wd[w] = dsum; }
    {
        float4* arow = (float4*)s_acc[w];
        arow[lane] = a0; arow[lane + 32] = a1; arow[lane + 64] = a2;
    }
    __syncthreads();

    // ---------------- merge the 16 warp-local softmax states --------------------
    if (w == 0) {
        float mm = (lane < NW) ? s_wm[lane] : -INFINITY;
        #pragma unroll
        for (int o = 16; o; o >>= 1)
            mm = fmaxf(mm, __shfl_xor_sync(0xffffffffu, mm, o));
        float sc = 0.f, dd = 0.f;
        if (lane < NW) {
            sc = __expf(s_wm[lane] - mm);            // 0 if warp fully masked
            s_wscale[lane] = sc;
            dd = s_wd[lane] * sc;
        }
        dd = warp_sum(dd);
        if (lane == 0) { s_gm = mm; s_gd = dd; }
    }
    __syncthreads();

    const float gm   = s_gm;
    const float ginv = 1.f / s_gd;

    // ctx[e] = (sum_w wscale[w] * acc[w][e]) / d
    if (tid < EE) {
        float c = 0.f;
        #pragma unroll
        for (int ww = 0; ww < NW; ++ww)
            c = fmaf(s_wscale[ww], s_acc[ww][tid], c);
        s_ctx[tid] = c * ginv;
    }

    // attn_weight output (masked -> exp(-inf)=0 exactly)
    {
        float* out_attn = out + BB + (size_t)b * SP1;
        for (int s = tid; s < SP1; s += NT)
            out_attn[s] = __expf(s_scores[s] - gm) * ginv;
    }
    __syncthreads();

    // ---------------- doc_repr = ctx @ W_v + b_v ; logits ------------------------
    {
        const int g  = w, h = lane;
        const int e0 = g * (EE / NW);                // 24-wide slabs
        float p = 0.f;
        #pragma unroll
        for (int j = 0; j < EE / NW; ++j)
            p = fmaf(s_ctx[e0 + j], W_v[(e0 + j) * HH + h], p);
        s_doc[g][h] = p;
    }
    __syncthreads();
    if (w == 0) {
        float dv = b_v[lane];
        #pragma unroll
        for (int g = 0; g < NW; ++g) dv += s_doc[g][lane];
        float lg = fmaf(dv, W_c[lane], s_q[lane] * W_c[HH + lane]);
        lg = warp_sum(lg);
        if (lane == 0) out[b] = lg + b_c[0];
    }
}

extern "C" void kernel_launch(void* const* d_in, const int* in_sizes, int n_in,
                              void* d_out, int out_size) {
    (void)in_sizes; (void)n_in; (void)out_size;
    sent_attn_kernel<<<BB, NT>>>(
        (const float*)d_in[0],   // embeddings
        (const int*  )d_in[1],   // masks
        (const float*)d_in[2],   // features
        (const float*)d_in[3],   // W_map
        (const float*)d_in[4],   // b_map
        (const float*)d_in[5],   // trainable
        (const float*)d_in[6],   // W_k
        (const float*)d_in[7],   // b_k
        (const float*)d_in[8],   // W_v
        (const float*)d_in[9],   // b_v
        (const float*)d_in[10],  // W_c
        (const float*)d_in[11],  // b_c
        (float*)d_out);
}

// round 3
// speedup vs baseline: 1.7212x; 1.0943x over previous
#include <cuda_runtime.h>
#include <math.h>

#define BB  2048
#define SS  512
#define EE  384
#define FF  28
#define HH  32
#define SP1 513          // S+1 positions (trainable prefix + S)
#define NW  16           // warps per block
#define NT  512          // threads per block

__device__ __forceinline__ float warp_sum(float v) {
    #pragma unroll
    for (int o = 16; o; o >>= 1) v += __shfl_xor_sync(0xffffffffu, v, o);
    return v;
}

__global__ __launch_bounds__(NT, 2)
void sent_attn_kernel(const float* __restrict__ emb,        // [B,S,E]
                      const int*   __restrict__ masks,      // [B,S]
                      const float* __restrict__ features,   // [B,F]
                      const float* __restrict__ W_map,      // [F,H]
                      const float* __restrict__ b_map,      // [H]
                      const float* __restrict__ trainable,  // [1,E]
                      const float* __restrict__ W_k,        // [E,H]
                      const float* __restrict__ b_k,        // [H]
                      const float* __restrict__ W_v,        // [E,H]
                      const float* __restrict__ b_v,        // [H]
                      const float* __restrict__ W_c,        // [2H,1]
                      const float* __restrict__ b_c,        // [1]
                      float*       __restrict__ out)        // [B] logits ++ [B,SP1] attn
{
    __shared__ __align__(16) float s_qk[EE];
    __shared__ __align__(16) float s_norm[EE];
    __shared__ __align__(16) float s_acc[NW][EE];
    __shared__ __align__(16) float s_ctx[EE];
    __shared__ float s_q[HH];
    __shared__ float s_scores[SP1];
    __shared__ short s_act[SS];
    __shared__ int   s_wcnt[NW], s_woff[NW + 1];
    __shared__ float s_wd[NW];
    __shared__ float s_doc[NW][HH];
    __shared__ float s_dotqbk, s_gd;

    const int b    = blockIdx.x;
    const int tid  = threadIdx.x;
    const int w    = tid >> 5;
    const int lane = tid & 31;

    // ---------------- prologue -------------------------------------------------
    // mask read + per-warp ballot (deterministic compaction), score init
    const int active = (masks[(size_t)b * SS + tid] == 0);
    const unsigned bal = __ballot_sync(0xffffffffu, active);
    if (lane == 0) s_wcnt[w] = __popc(bal);
    s_scores[tid] = -INFINITY;
    if (tid == 0) s_scores[SS] = -INFINITY;

    if (w == 0) {
        float acc = b_map[lane];
        const float* fb = features + b * FF;
        #pragma unroll
        for (int f = 0; f < FF; ++f)
            acc = fmaf(fb[f], W_map[f * HH + lane], acc);
        s_q[lane] = acc;
    } else if (w == 1) {
        float ss = 0.f;
        #pragma unroll
        for (int j = 0; j < EE / 32; ++j) {
            float t = trainable[lane + 32 * j];
            ss = fmaf(t, t, ss);
        }
        ss = warp_sum(ss);
        float inv = rsqrtf(ss);
        #pragma unroll
        for (int j = 0; j < EE / 32; ++j)
            s_norm[lane + 32 * j] = trainable[lane + 32 * j] * inv;
    }
    __syncthreads();

    // warp 0: exclusive scan of the 16 warp counts
    if (w == 0) {
        int c = (lane < NW) ? s_wcnt[lane] : 0;
        int sc = c;
        #pragma unroll
        for (int o = 1; o < NW; o <<= 1) {
            int t = __shfl_up_sync(0xffffffffu, sc, o);
            if (lane >= o) sc += t;
        }
        if (lane < NW) s_woff[lane + 1] = sc;
        if (lane == 0) s_woff[0] = 0;
    }

    // qk = W_k @ q  (L2-resident weights)
    {
        float qv = s_q[lane];
        #pragma unroll
        for (int i = 0; i < EE / NW; ++i) {          // 24 iterations
            int e = w + i * NW;
            float p = W_k[e * HH + lane] * qv;
            p = warp_sum(p);
            if (lane == 0) s_qk[e] = p;
        }
    }
    if (tid == 0) {
        float acc = 0.f;
        #pragma unroll
        for (int h = 0; h < HH; ++h) acc = fmaf(s_q[h], b_k[h], acc);
        s_dotqbk = acc;
    }
    __syncthreads();

    // compacted active-row list (deterministic: ordered by tid)
    if (active) {
        int pos = s_woff[w] + __popc(bal & ((1u << lane) - 1u));
        s_act[pos] = (short)tid;
    }

    // ---------------- main pass: direct-exp softmax, 2 rows/warp/iter ----------
    const float dq    = s_dotqbk;
    const float scale = 0.17677669529663687f;        // 1/sqrt(32)
    const float4* qk4 = (const float4*)s_qk;
    float4 k0 = qk4[lane], k1 = qk4[lane + 32], k2 = qk4[lane + 64];

    float  dsum = 0.f;
    float4 a0 = {0.f,0.f,0.f,0.f}, a1 = {0.f,0.f,0.f,0.f}, a2 = {0.f,0.f,0.f,0.f};

    // warp 0 seeds with the (never-masked) trainable prefix position
    if (w == 0) {
        const float4* n4 = (const float4*)s_norm;
        float4 v0 = n4[lane], v1 = n4[lane + 32], v2 = n4[lane + 64];
        float p = v0.x*k0.x + v0.y*k0.y + v0.z*k0.z + v0.w*k0.w;
        p      += v1.x*k1.x + v1.y*k1.y + v1.z*k1.z + v1.w*k1.w;
        p      += v2.x*k2.x + v2.y*k2.y + v2.z*k2.z + v2.w*k2.w;
        p = warp_sum(p);
        float sc = (p + dq) * scale;
        float wt = __expf(sc);
        if (lane == 0) s_scores[0] = sc;
        dsum = wt;
        a0.x = wt*v0.x; a0.y = wt*v0.y; a0.z = wt*v0.z; a0.w = wt*v0.w;
        a1.x = wt*v1.x; a1.y = wt*v1.y; a1.z = wt*v1.z; a1.w = wt*v1.w;
        a2.x = wt*v2.x; a2.y = wt*v2.y; a2.z = wt*v2.z; a2.w = wt*v2.w;
    }
    __syncthreads();

    const int n_act = s_woff[NW];
    const float4* erow_base = (const float4*)emb + (size_t)b * SS * (EE / 4);

    for (int base = 2 * w; base < n_act; base += 2 * NW) {
        const int sA = s_act[base];
        const int sB = (base + 1 < n_act) ? (int)s_act[base + 1] : -1;

        const float4* rA = erow_base + (size_t)sA * (EE / 4);
        float4 vA0 = __ldcs(rA + lane);
        float4 vA1 = __ldcs(rA + lane + 32);
        float4 vA2 = __ldcs(rA + lane + 64);

        float4 vB0, vB1, vB2;
        if (sB >= 0) {
            const float4* rB = erow_base + (size_t)sB * (EE / 4);
            vB0 = __ldcs(rB + lane);
            vB1 = __ldcs(rB + lane + 32);
            vB2 = __ldcs(rB + lane + 64);
        }

        float pA = vA0.x*k0.x + vA0.y*k0.y + vA0.z*k0.z + vA0.w*k0.w;
        pA      += vA1.x*k1.x + vA1.y*k1.y + vA1.z*k1.z + vA1.w*k1.w;
        pA      += vA2.x*k2.x + vA2.y*k2.y + vA2.z*k2.z + vA2.w*k2.w;
        float pB = 0.f;
        if (sB >= 0) {
            pB = vB0.x*k0.x + vB0.y*k0.y + vB0.z*k0.z + vB0.w*k0.w;
            pB += vB1.x*k1.x + vB1.y*k1.y + vB1.z*k1.z + vB1.w*k1.w;
            pB += vB2.x*k2.x + vB2.y*k2.y + vB2.z*k2.z + vB2.w*k2.w;
        }
        // two overlapped shuffle-reduce chains
        #pragma unroll
        for (int o = 16; o; o >>= 1) {
            pA += __shfl_xor_sync(0xffffffffu, pA, o);
            pB += __shfl_xor_sync(0xffffffffu, pB, o);
        }

        float scA = (pA + dq) * scale;
        float wA  = __expf(scA);
        if (lane == 0) s_scores[sA + 1] = scA;
        dsum += wA;
        a0.x = fmaf(wA, vA0.x, a0.x); a0.y = fmaf(wA, vA0.y, a0.y);
        a0.z = fmaf(wA, vA0.z, a0.z); a0.w = fmaf(wA, vA0.w, a0.w);
        a1.x = fmaf(wA, vA1.x, a1.x); a1.y = fmaf(wA, vA1.y, a1.y);
        a1.z = fmaf(wA, vA1.z, a1.z); a1.w = fmaf(wA, vA1.w, a1.w);
        a2.x = fmaf(wA, vA2.x, a2.x); a2.y = fmaf(wA, vA2.y, a2.y);
        a2.z = fmaf(wA, vA2.z, a2.z); a2.w = fmaf(wA, vA2.w, a2.w);

        if (sB >= 0) {
            float scB = (pB + dq) * scale;
            float wB  = __expf(scB);
            if (lane == 0) s_scores[sB + 1] = scB;
            dsum += wB;
            a0.x = fmaf(wB, vB0.x, a0.x); a0.y = fmaf(wB, vB0.y, a0.y);
            a0.z = fmaf(wB, vB0.z, a0.z); a0.w = fmaf(wB, vB0.w, a0.w);
            a1.x = fmaf(wB, vB1.x, a1.x); a1.y = fmaf(wB, vB1.y, a1.y);
            a1.z = fmaf(wB, vB1.z, a1.z); a1.w = fmaf(wB, vB1.w, a1.w);
            a2.x = fmaf(wB, vB2.x, a2.x); a2.y = fmaf(wB, vB2.y, a2.y);
            a2.z = fmaf(wB, vB2.z, a2.z); a2.w = fmaf(wB, vB2.w, a2.w);
        }
    }

    if (lane == 0) s_wd[w] = dsum;
    {
        float4* arow = (float4*)s_acc[w];
        arow[lane] = a0; arow[lane + 32] = a1; arow[lane + 64] = a2;
    }
    __syncthreads();

    // ---------------- merge: total denominator ----------------------------------
    if (w == 0) {
        float dd = (lane < NW) ? s_wd[lane] : 0.f;
        dd = warp_sum(dd);
        if (lane == 0) s_gd = dd;
    }
    __syncthreads();

    const float ginv = 1.f / s_gd;

    // ctx[e] = (sum_w acc[w][e]) / D
    if (tid < EE) {
        float c = 0.f;
        #pragma unroll
        for (int ww = 0; ww < NW; ++ww)
            c += s_acc[ww][tid];
        s_ctx[tid] = c * ginv;
    }

    // attn_weight output (masked rows: exp(-inf)=0 exactly)
    {
        float* out_attn = out + BB + (size_t)b * SP1;
        for (int s = tid; s < SP1; s += NT)
            out_attn[s] = __expf(s_scores[s]) * ginv;
    }
    __syncthreads();

    // ---------------- doc_repr = ctx @ W_v + b_v ; logits ------------------------
    {
        const int g  = w, h = lane;
        const int e0 = g * (EE / NW);                // 24-wide slabs
        float p = 0.f;
        #pragma unroll
        for (int j = 0; j < EE / NW; ++j)
            p = fmaf(s_ctx[e0 + j], W_v[(e0 + j) * HH + h], p);
        s_doc[g][h] = p;
    }
    __syncthreads();
    if (w == 0) {
        float dv = b_v[lane];
        #pragma unroll
        for (int g = 0; g < NW; ++g) dv += s_doc[g][lane];
        float lg = fmaf(dv, W_c[lane], s_q[lane] * W_c[HH + lane]);
        lg = warp_sum(lg);
        if (lane == 0) out[b] = lg + b_c[0];
    }
}

extern "C" void kernel_launch(void* const* d_in, const int* in_sizes, int n_in,
                              void* d_out, int out_size) {
    (void)in_sizes; (void)n_in; (void)out_size;
    sent_attn_kernel<<<BB, NT>>>(
        (const float*)d_in[0],   // embeddings
        (const int*  )d_in[1],   // masks
        (const float*)d_in[2],   // features
        (const float*)d_in[3],   // W_map
        (const float*)d_in[4],   // b_map
        (const float*)d_in[5],   // trainable
        (const float*)d_in[6],   // W_k
        (const float*)d_in[7],   // b_k
        (const float*)d_in[8],   // W_v
        (const float*)d_in[9],   // b_v
        (const float*)d_in[10],  // W_c
        (const float*)d_in[11],  // b_c
        (float*)d_out);
}